// round 15
// baseline (speedup 1.0000x reference)
#include <cuda_runtime.h>
#include <cuda_fp16.h>
#include <cuda_bf16.h>
#include <cstdint>

// Problem constants (fixed by the reference generator)
#define NNODES 100000
#define DIM    128          // FAC_K * DIM_K = 4 * 32
#define FAC_K  4
#define DIM_K  32
#define EMAX   1600000

#define SCAN_CHUNK 2048
#define SCAN_NBLK  ((NNODES + SCAN_CHUNK - 1) / SCAN_CHUNK)   // 49

// Scratch (node-major: fac[n*128 + f*32 + k])
__device__ float  g_fac[(size_t)NNODES * DIM];
__device__ float  g_new[(size_t)NNODES * DIM];
__device__ __half g_fach[(size_t)NNODES * DIM];   // fp16 copy of fac for gathers
__device__ int    g_deg[NNODES];
__device__ int    g_start[NNODES + 1];
__device__ int    g_cursor[NNODES];
__device__ int    g_colS[EMAX];
__device__ int    g_bsums[64];
__device__ int    g_boffs[64];

// ---------------------------------------------------------------------------
// Blackwell packed fp32 helpers (double-rate FFMA2 — exact fp32 semantics)
// ---------------------------------------------------------------------------
__device__ __forceinline__ unsigned long long pk2(float lo, float hi) {
    unsigned long long r;
    asm("mov.b64 %0, {%1, %2};" : "=l"(r) : "f"(lo), "f"(hi));
    return r;
}
__device__ __forceinline__ void fma2(unsigned long long& d,
                                     unsigned long long a, unsigned long long b) {
    asm("fma.rn.f32x2 %0, %1, %2, %0;" : "+l"(d) : "l"(a), "l"(b));
}
__device__ __forceinline__ void upk2(unsigned long long v, float& lo, float& hi) {
    asm("mov.b64 {%0, %1}, %2;" : "=f"(lo), "=f"(hi) : "l"(v));
}

// ---------------------------------------------------------------------------
// GEMM + leakyReLU + per-factor L2 norm.  fp32x2 packed FMA mainloop.
// Writes fac (fp32) and fac_h (fp16 tail table).
// ---------------------------------------------------------------------------
__global__ void __launch_bounds__(256, 2)
gemm_kernel(const float* __restrict__ emb, const float* __restrict__ W,
            const float* __restrict__ b, float* __restrict__ fac,
            __half* __restrict__ fach) {
    extern __shared__ float sm[];
    float* sW = sm;               // 128*128 floats
    float* sA = sm + DIM * DIM;   // 64*128 floats

    const int tid  = threadIdx.x;
    const int lane = tid & 31;
    const int w    = tid >> 5;

    // W'[d][c] = W[f][d][k] + b[f][k],  c = f*32+k
    for (int i = tid; i < DIM * DIM; i += 256) {
        int d = i >> 7, c = i & 127;
        int f = c >> 5, k = c & 31;
        sW[i] = W[(f * DIM + d) * DIM_K + k] + b[f * DIM_K + k];
    }
    __syncthreads();

    const float4* sW4 = (const float4*)sW;
    const int TILE = 64;

    for (int base = blockIdx.x * TILE; base < NNODES; base += gridDim.x * TILE) {
        int rows = NNODES - base; if (rows > TILE) rows = TILE;
        __syncthreads();
        const float4* src = (const float4*)(emb + (size_t)base * DIM);
        float4* dstA = (float4*)sA;
        for (int i = tid; i < rows * (DIM / 4); i += 256) dstA[i] = src[i];
        __syncthreads();

        unsigned long long axy[8], azw[8];
        #pragma unroll
        for (int r = 0; r < 8; r++) { axy[r] = pk2(0.f, 0.f); azw[r] = pk2(0.f, 0.f); }

        #pragma unroll 2
        for (int d0 = 0; d0 < DIM; d0 += 4) {
            unsigned long long wxy[4], wzw[4];
            #pragma unroll
            for (int i = 0; i < 4; i++) {
                float4 w4 = sW4[(d0 + i) * 32 + lane];
                wxy[i] = pk2(w4.x, w4.y);
                wzw[i] = pk2(w4.z, w4.w);
            }
            #pragma unroll
            for (int r = 0; r < 8; r++) {
                float4 a4 = *(const float4*)&sA[(w * 8 + r) * DIM + d0];
                unsigned long long aa;
                aa = pk2(a4.x, a4.x); fma2(axy[r], aa, wxy[0]); fma2(azw[r], aa, wzw[0]);
                aa = pk2(a4.y, a4.y); fma2(axy[r], aa, wxy[1]); fma2(azw[r], aa, wzw[1]);
                aa = pk2(a4.z, a4.z); fma2(axy[r], aa, wxy[2]); fma2(azw[r], aa, wzw[2]);
                aa = pk2(a4.w, a4.w); fma2(axy[r], aa, wxy[3]); fma2(azw[r], aa, wzw[3]);
            }
        }

        #pragma unroll
        for (int r = 0; r < 8; r++) {
            int gr = base + w * 8 + r;
            if (gr >= NNODES) break;
            float4 v;
            upk2(axy[r], v.x, v.y);
            upk2(azw[r], v.z, v.w);
            v.x = v.x > 0.f ? v.x : 0.2f * v.x;
            v.y = v.y > 0.f ? v.y : 0.2f * v.y;
            v.z = v.z > 0.f ? v.z : 0.2f * v.z;
            v.w = v.w > 0.f ? v.w : 0.2f * v.w;
            float s = v.x*v.x + v.y*v.y + v.z*v.z + v.w*v.w;
            s += __shfl_xor_sync(0xFFFFFFFFu, s, 1);
            s += __shfl_xor_sync(0xFFFFFFFFu, s, 2);
            s += __shfl_xor_sync(0xFFFFFFFFu, s, 4);   // 8-lane group = one factor
            float inv = 1.0f / fmaxf(sqrtf(s), 1e-12f);
            v.x *= inv; v.y *= inv; v.z *= inv; v.w *= inv;
            ((float4*)(fac + (size_t)gr * DIM))[lane] = v;
            __half2 h0 = __floats2half2_rn(v.x, v.y);
            __half2 h1 = __floats2half2_rn(v.z, v.w);
            uint2 u;
            u.x = *(unsigned int*)&h0;
            u.y = *(unsigned int*)&h1;
            ((uint2*)fach)[(size_t)gr * 32 + lane] = u;
        }
    }
}

// ---------------------------------------------------------------------------
// CSR build: histogram -> 3-phase multi-block scan -> scatter of col ids.
// ---------------------------------------------------------------------------
__global__ void zero_deg_kernel(int* __restrict__ deg) {
    int i = blockIdx.x * blockDim.x + threadIdx.x;
    if (i < NNODES) deg[i] = 0;
}

__global__ void hist_kernel(const int* __restrict__ row, int E, int* __restrict__ deg) {
    for (int e = blockIdx.x * blockDim.x + threadIdx.x; e < E; e += gridDim.x * blockDim.x)
        atomicAdd(&deg[row[e]], 1);
}

__global__ void __launch_bounds__(256)
scan_partial_kernel(const int* __restrict__ deg, int* __restrict__ bsums) {
    const int tid  = threadIdx.x;
    const int lane = tid & 31;
    const int wid  = tid >> 5;
    const int base = blockIdx.x * SCAN_CHUNK;
    int s = 0;
    #pragma unroll
    for (int k = 0; k < SCAN_CHUNK / 256; k++) {
        int idx = base + tid + k * 256;
        if (idx < NNODES) s += deg[idx];
    }
    s += __shfl_down_sync(0xFFFFFFFFu, s, 16);
    s += __shfl_down_sync(0xFFFFFFFFu, s, 8);
    s += __shfl_down_sync(0xFFFFFFFFu, s, 4);
    s += __shfl_down_sync(0xFFFFFFFFu, s, 2);
    s += __shfl_down_sync(0xFFFFFFFFu, s, 1);
    __shared__ int ws[8];
    if (lane == 0) ws[wid] = s;
    __syncthreads();
    if (wid == 0) {
        int v = (lane < 8) ? ws[lane] : 0;
        v += __shfl_down_sync(0xFFFFFFFFu, v, 4);
        v += __shfl_down_sync(0xFFFFFFFFu, v, 2);
        v += __shfl_down_sync(0xFFFFFFFFu, v, 1);
        if (lane == 0) bsums[blockIdx.x] = v;
    }
}

__global__ void scan_sums_kernel(const int* __restrict__ bsums, int* __restrict__ boffs,
                                 int* __restrict__ start) {
    __shared__ int buf[64];
    int tid = threadIdx.x;                         // 64 threads
    int v = (tid < SCAN_NBLK) ? bsums[tid] : 0;
    buf[tid] = v;
    __syncthreads();
    #pragma unroll
    for (int off = 1; off < 64; off <<= 1) {
        int u = (tid >= off) ? buf[tid - off] : 0;
        __syncthreads();
        buf[tid] += u;
        __syncthreads();
    }
    if (tid < SCAN_NBLK) boffs[tid] = buf[tid] - v;   // exclusive
    if (tid == 63) start[NNODES] = buf[63];           // total edge count
}

__global__ void __launch_bounds__(256)
scan_final_kernel(const int* __restrict__ deg, const int* __restrict__ boffs,
                  int* __restrict__ start, int* __restrict__ cursor) {
    const int tid  = threadIdx.x;
    const int lane = tid & 31;
    const int wid  = tid >> 5;
    const int base = blockIdx.x * SCAN_CHUNK + tid * 8;

    int v[8];
    #pragma unroll
    for (int j = 0; j < 8; j++) {
        int idx = base + j;
        v[j] = (idx < NNODES) ? deg[idx] : 0;
    }
    int tsum = 0;
    #pragma unroll
    for (int j = 0; j < 8; j++) { int x = v[j]; v[j] = tsum; tsum += x; }

    int inc = tsum;
    #pragma unroll
    for (int off = 1; off < 32; off <<= 1) {
        int u = __shfl_up_sync(0xFFFFFFFFu, inc, off);
        if (lane >= off) inc += u;
    }
    int wexcl = inc - tsum;

    __shared__ int ws[8], wo[8];
    if (lane == 31) ws[wid] = inc;
    __syncthreads();
    if (tid < 8) {
        int e = 0;
        for (int k = 0; k < tid; k++) e += ws[k];
        wo[tid] = e;
    }
    __syncthreads();

    int off0 = boffs[blockIdx.x] + wo[wid] + wexcl;
    #pragma unroll
    for (int j = 0; j < 8; j++) {
        int idx = base + j;
        if (idx < NNODES) {
            int e = off0 + v[j];
            start[idx]  = e;
            cursor[idx] = e;
        }
    }
}

__global__ void scatter_kernel(const int* __restrict__ row, const int* __restrict__ col,
                               int E, int* __restrict__ cursor, int* __restrict__ colS) {
    for (int e = blockIdx.x * blockDim.x + threadIdx.x; e < E; e += gridDim.x * blockDim.x) {
        int r = row[e];
        int pos = atomicAdd(&cursor[r], 1);
        colS[pos] = col[e];
    }
}

// ---------------------------------------------------------------------------
// Fused per-iteration kernel: one warp per destination node.
// v3: warp-wide column prefetch (one coalesced LDG per 32 edges, shfl
// broadcast -> no dependent scalar load on the gather path) + batches of
// 8 edges with MLP-8 tail gathers + 8 interleaved dot/softmax shfl chains.
// ---------------------------------------------------------------------------
__global__ void __launch_bounds__(256)
fused_edge_norm(const float* __restrict__ head_src,
                const float* __restrict__ fac,
                const __half* __restrict__ fach,
                const int* __restrict__ start,
                const int* __restrict__ colS,
                float* __restrict__ out) {
    const int lane = threadIdx.x & 31;
    const int n = (blockIdx.x * blockDim.x + threadIdx.x) >> 5;
    if (n >= NNODES) return;

    const size_t base = (size_t)n * DIM;
    float4 h = __ldg((const float4*)(head_src + base) + lane);
    int s     = __ldg(start + n);
    int e_end = __ldg(start + n + 1);

    const uint2* th = (const uint2*)fach;

    float4 acc = make_float4(0.f, 0.f, 0.f, 0.f);

    for (int chunk = s; chunk < e_end; chunk += 32) {
        int cnt = e_end - chunk; if (cnt > 32) cnt = 32;
        // one coalesced load fetches up to 32 column indices
        int myc = (lane < cnt) ? __ldg(colS + chunk + lane) : 0;

        for (int j0 = 0; j0 < cnt; j0 += 8) {
            int nb = cnt - j0; if (nb > 8) nb = 8;

            // MLP-8 gather: addresses come from register shfl, not memory
            uint2 t[8];
            #pragma unroll
            for (int j = 0; j < 8; j++) {
                if (j < nb) {
                    int c = __shfl_sync(0xFFFFFFFFu, myc, j0 + j);
                    t[j] = __ldg(th + (size_t)c * 32 + lane);
                } else {
                    t[j] = make_uint2(0u, 0u);   // safe padding: dp=0
                }
            }

            // 8 interleaved dot chains
            float dp[8];
            #pragma unroll
            for (int j = 0; j < 8; j++) {
                float2 f0 = __half22float2(*(__half2*)&t[j].x);
                float2 f1 = __half22float2(*(__half2*)&t[j].y);
                dp[j] = h.x*f0.x + h.y*f0.y + h.z*f1.x + h.w*f1.y;
            }
            #pragma unroll
            for (int j = 0; j < 8; j++) dp[j] += __shfl_xor_sync(0xFFFFFFFFu, dp[j], 1);
            #pragma unroll
            for (int j = 0; j < 8; j++) dp[j] += __shfl_xor_sync(0xFFFFFFFFu, dp[j], 2);
            #pragma unroll
            for (int j = 0; j < 8; j++) dp[j] += __shfl_xor_sync(0xFFFFFFFFu, dp[j], 4);

            float ea[8], s1[8], p[8];
            #pragma unroll
            for (int j = 0; j < 8; j++) ea[j] = __expf(dp[j]);
            #pragma unroll
            for (int j = 0; j < 8; j++) s1[j] = ea[j] + __shfl_xor_sync(0xFFFFFFFFu, ea[j], 8);
            #pragma unroll
            for (int j = 0; j < 8; j++) {
                float st = s1[j] + __shfl_xor_sync(0xFFFFFFFFu, s1[j], 16);
                p[j] = __fdividef(ea[j], st);
            }

            #pragma unroll
            for (int j = 0; j < 8; j++) {
                if (j < nb) {
                    float2 f0 = __half22float2(*(__half2*)&t[j].x);
                    float2 f1 = __half22float2(*(__half2*)&t[j].y);
                    acc.x += p[j] * f0.x; acc.y += p[j] * f0.y;
                    acc.z += p[j] * f1.x; acc.w += p[j] * f1.y;
                }
            }
        }
    }

    // residual base is ALWAYS the original fac (both iterations), fp32-exact
    float4 f = (head_src == fac) ? h : __ldg((const float4*)(fac + base) + lane);
    float4 v = make_float4(f.x + acc.x, f.y + acc.y, f.z + acc.z, f.w + acc.w);
    float ss = v.x*v.x + v.y*v.y + v.z*v.z + v.w*v.w;
    ss += __shfl_xor_sync(0xFFFFFFFFu, ss, 1);
    ss += __shfl_xor_sync(0xFFFFFFFFu, ss, 2);
    ss += __shfl_xor_sync(0xFFFFFFFFu, ss, 4);
    float inv = 1.0f / fmaxf(sqrtf(ss), 1e-12f);
    v.x *= inv; v.y *= inv; v.z *= inv; v.w *= inv;
    ((float4*)(out + base))[lane] = v;
}

// ---------------------------------------------------------------------------
extern "C" void kernel_launch(void* const* d_in, const int* in_sizes, int n_in,
                              void* d_out, int out_size) {
    const float* all_emb = (const float*)d_in[0];
    const float* W       = (const float*)d_in[1];
    const float* b       = (const float*)d_in[2];
    const int*   row     = (const int*)  d_in[3];
    const int*   col     = (const int*)  d_in[4];
    int          E       = in_sizes[3];
    if (E > EMAX) E = EMAX;
    float*       out     = (float*)d_out;

    float *fac, *nf;
    __half* fach;
    int *deg, *start, *cursor, *colS, *bsums, *boffs;
    cudaGetSymbolAddress((void**)&fac,    g_fac);
    cudaGetSymbolAddress((void**)&nf,     g_new);
    cudaGetSymbolAddress((void**)&fach,   g_fach);
    cudaGetSymbolAddress((void**)&deg,    g_deg);
    cudaGetSymbolAddress((void**)&start,  g_start);
    cudaGetSymbolAddress((void**)&cursor, g_cursor);
    cudaGetSymbolAddress((void**)&colS,   g_colS);
    cudaGetSymbolAddress((void**)&bsums,  g_bsums);
    cudaGetSymbolAddress((void**)&boffs,  g_boffs);

    const int smem = (DIM * DIM + 64 * DIM) * sizeof(float);  // 96 KB
    cudaFuncSetAttribute(gemm_kernel, cudaFuncAttributeMaxDynamicSharedMemorySize, smem);

    // Phase 1: factor embeddings (fp32x2 packed FMA) + fp16 tail table
    gemm_kernel<<<1563, 256, smem>>>(all_emb, W, b, fac, fach);

    // Phase 2: CSR build (row/col identical for both iterations -> build once)
    zero_deg_kernel<<<(NNODES + 255) / 256, 256>>>(deg);
    hist_kernel<<<2048, 256>>>(row, E, deg);
    scan_partial_kernel<<<SCAN_NBLK, 256>>>(deg, bsums);
    scan_sums_kernel<<<1, 64>>>(bsums, boffs, start);
    scan_final_kernel<<<SCAN_NBLK, 256>>>(deg, boffs, start, cursor);
    scatter_kernel<<<2048, 256>>>(row, col, E, cursor, colS);

    // Phase 3: two fused propagate+norm iterations (warp per node)
    const int blocks = (NNODES * 32 + 255) / 256;   // 12500
    fused_edge_norm<<<blocks, 256>>>(fac, fac, fach, start, colS, nf);
    fused_edge_norm<<<blocks, 256>>>(nf,  fac, fach, start, colS, out);
}

// round 16
// speedup vs baseline: 1.2604x; 1.2604x over previous
#include <cuda_runtime.h>
#include <cuda_fp16.h>
#include <cuda_bf16.h>
#include <cstdint>

// Problem constants (fixed by the reference generator)
#define NNODES 100000
#define DIM    128          // FAC_K * DIM_K = 4 * 32
#define FAC_K  4
#define DIM_K  32
#define EMAX   1600000

#define SCAN_CHUNK 2048
#define SCAN_NBLK  ((NNODES + SCAN_CHUNK - 1) / SCAN_CHUNK)   // 49

// Scratch (node-major: fac[n*128 + f*32 + k])
__device__ float  g_fac[(size_t)NNODES * DIM];
__device__ float  g_new[(size_t)NNODES * DIM];
__device__ __half g_fach[(size_t)NNODES * DIM];   // fp16 copy of fac for gathers
__device__ int    g_deg[NNODES];
__device__ int    g_start[NNODES + 1];
__device__ int    g_cursor[NNODES];
__device__ int    g_colS[EMAX];
__device__ int    g_bsums[64];
__device__ int    g_boffs[64];

// ---------------------------------------------------------------------------
// Blackwell packed fp32 helpers (double-rate FFMA2 — exact fp32 semantics)
// ---------------------------------------------------------------------------
__device__ __forceinline__ unsigned long long pk2(float lo, float hi) {
    unsigned long long r;
    asm("mov.b64 %0, {%1, %2};" : "=l"(r) : "f"(lo), "f"(hi));
    return r;
}
__device__ __forceinline__ void fma2(unsigned long long& d,
                                     unsigned long long a, unsigned long long b) {
    asm("fma.rn.f32x2 %0, %1, %2, %0;" : "+l"(d) : "l"(a), "l"(b));
}
__device__ __forceinline__ void upk2(unsigned long long v, float& lo, float& hi) {
    asm("mov.b64 {%0, %1}, %2;" : "=f"(lo), "=f"(hi) : "l"(v));
}

// ---------------------------------------------------------------------------
// GEMM + leakyReLU + per-factor L2 norm.  fp32x2 packed FMA mainloop.
// Writes fac (fp32) and fac_h (fp16 tail table).
// ---------------------------------------------------------------------------
__global__ void __launch_bounds__(256, 2)
gemm_kernel(const float* __restrict__ emb, const float* __restrict__ W,
            const float* __restrict__ b, float* __restrict__ fac,
            __half* __restrict__ fach) {
    extern __shared__ float sm[];
    float* sW = sm;               // 128*128 floats
    float* sA = sm + DIM * DIM;   // 64*128 floats

    const int tid  = threadIdx.x;
    const int lane = tid & 31;
    const int w    = tid >> 5;

    // W'[d][c] = W[f][d][k] + b[f][k],  c = f*32+k
    for (int i = tid; i < DIM * DIM; i += 256) {
        int d = i >> 7, c = i & 127;
        int f = c >> 5, k = c & 31;
        sW[i] = W[(f * DIM + d) * DIM_K + k] + b[f * DIM_K + k];
    }
    __syncthreads();

    const float4* sW4 = (const float4*)sW;
    const int TILE = 64;

    for (int base = blockIdx.x * TILE; base < NNODES; base += gridDim.x * TILE) {
        int rows = NNODES - base; if (rows > TILE) rows = TILE;
        __syncthreads();
        const float4* src = (const float4*)(emb + (size_t)base * DIM);
        float4* dstA = (float4*)sA;
        for (int i = tid; i < rows * (DIM / 4); i += 256) dstA[i] = src[i];
        __syncthreads();

        unsigned long long axy[8], azw[8];
        #pragma unroll
        for (int r = 0; r < 8; r++) { axy[r] = pk2(0.f, 0.f); azw[r] = pk2(0.f, 0.f); }

        #pragma unroll 2
        for (int d0 = 0; d0 < DIM; d0 += 4) {
            unsigned long long wxy[4], wzw[4];
            #pragma unroll
            for (int i = 0; i < 4; i++) {
                float4 w4 = sW4[(d0 + i) * 32 + lane];
                wxy[i] = pk2(w4.x, w4.y);
                wzw[i] = pk2(w4.z, w4.w);
            }
            #pragma unroll
            for (int r = 0; r < 8; r++) {
                float4 a4 = *(const float4*)&sA[(w * 8 + r) * DIM + d0];
                unsigned long long aa;
                aa = pk2(a4.x, a4.x); fma2(axy[r], aa, wxy[0]); fma2(azw[r], aa, wzw[0]);
                aa = pk2(a4.y, a4.y); fma2(axy[r], aa, wxy[1]); fma2(azw[r], aa, wzw[1]);
                aa = pk2(a4.z, a4.z); fma2(axy[r], aa, wxy[2]); fma2(azw[r], aa, wzw[2]);
                aa = pk2(a4.w, a4.w); fma2(axy[r], aa, wxy[3]); fma2(azw[r], aa, wzw[3]);
            }
        }

        #pragma unroll
        for (int r = 0; r < 8; r++) {
            int gr = base + w * 8 + r;
            if (gr >= NNODES) break;
            float4 v;
            upk2(axy[r], v.x, v.y);
            upk2(azw[r], v.z, v.w);
            v.x = v.x > 0.f ? v.x : 0.2f * v.x;
            v.y = v.y > 0.f ? v.y : 0.2f * v.y;
            v.z = v.z > 0.f ? v.z : 0.2f * v.z;
            v.w = v.w > 0.f ? v.w : 0.2f * v.w;
            float s = v.x*v.x + v.y*v.y + v.z*v.z + v.w*v.w;
            s += __shfl_xor_sync(0xFFFFFFFFu, s, 1);
            s += __shfl_xor_sync(0xFFFFFFFFu, s, 2);
            s += __shfl_xor_sync(0xFFFFFFFFu, s, 4);   // 8-lane group = one factor
            float inv = 1.0f / fmaxf(sqrtf(s), 1e-12f);
            v.x *= inv; v.y *= inv; v.z *= inv; v.w *= inv;
            ((float4*)(fac + (size_t)gr * DIM))[lane] = v;
            __half2 h0 = __floats2half2_rn(v.x, v.y);
            __half2 h1 = __floats2half2_rn(v.z, v.w);
            uint2 u;
            u.x = *(unsigned int*)&h0;
            u.y = *(unsigned int*)&h1;
            ((uint2*)fach)[(size_t)gr * 32 + lane] = u;
        }
    }
}

// ---------------------------------------------------------------------------
// CSR build: histogram -> 3-phase multi-block scan -> scatter of col ids.
// ---------------------------------------------------------------------------
__global__ void zero_deg_kernel(int* __restrict__ deg) {
    int i = blockIdx.x * blockDim.x + threadIdx.x;
    if (i < NNODES) deg[i] = 0;
}

__global__ void hist_kernel(const int* __restrict__ row, int E, int* __restrict__ deg) {
    for (int e = blockIdx.x * blockDim.x + threadIdx.x; e < E; e += gridDim.x * blockDim.x)
        atomicAdd(&deg[row[e]], 1);
}

__global__ void __launch_bounds__(256)
scan_partial_kernel(const int* __restrict__ deg, int* __restrict__ bsums) {
    const int tid  = threadIdx.x;
    const int lane = tid & 31;
    const int wid  = tid >> 5;
    const int base = blockIdx.x * SCAN_CHUNK;
    int s = 0;
    #pragma unroll
    for (int k = 0; k < SCAN_CHUNK / 256; k++) {
        int idx = base + tid + k * 256;
        if (idx < NNODES) s += deg[idx];
    }
    s += __shfl_down_sync(0xFFFFFFFFu, s, 16);
    s += __shfl_down_sync(0xFFFFFFFFu, s, 8);
    s += __shfl_down_sync(0xFFFFFFFFu, s, 4);
    s += __shfl_down_sync(0xFFFFFFFFu, s, 2);
    s += __shfl_down_sync(0xFFFFFFFFu, s, 1);
    __shared__ int ws[8];
    if (lane == 0) ws[wid] = s;
    __syncthreads();
    if (wid == 0) {
        int v = (lane < 8) ? ws[lane] : 0;
        v += __shfl_down_sync(0xFFFFFFFFu, v, 4);
        v += __shfl_down_sync(0xFFFFFFFFu, v, 2);
        v += __shfl_down_sync(0xFFFFFFFFu, v, 1);
        if (lane == 0) bsums[blockIdx.x] = v;
    }
}

__global__ void scan_sums_kernel(const int* __restrict__ bsums, int* __restrict__ boffs,
                                 int* __restrict__ start) {
    __shared__ int buf[64];
    int tid = threadIdx.x;                         // 64 threads
    int v = (tid < SCAN_NBLK) ? bsums[tid] : 0;
    buf[tid] = v;
    __syncthreads();
    #pragma unroll
    for (int off = 1; off < 64; off <<= 1) {
        int u = (tid >= off) ? buf[tid - off] : 0;
        __syncthreads();
        buf[tid] += u;
        __syncthreads();
    }
    if (tid < SCAN_NBLK) boffs[tid] = buf[tid] - v;   // exclusive
    if (tid == 63) start[NNODES] = buf[63];           // total edge count
}

__global__ void __launch_bounds__(256)
scan_final_kernel(const int* __restrict__ deg, const int* __restrict__ boffs,
                  int* __restrict__ start, int* __restrict__ cursor) {
    const int tid  = threadIdx.x;
    const int lane = tid & 31;
    const int wid  = tid >> 5;
    const int base = blockIdx.x * SCAN_CHUNK + tid * 8;

    int v[8];
    #pragma unroll
    for (int j = 0; j < 8; j++) {
        int idx = base + j;
        v[j] = (idx < NNODES) ? deg[idx] : 0;
    }
    int tsum = 0;
    #pragma unroll
    for (int j = 0; j < 8; j++) { int x = v[j]; v[j] = tsum; tsum += x; }

    int inc = tsum;
    #pragma unroll
    for (int off = 1; off < 32; off <<= 1) {
        int u = __shfl_up_sync(0xFFFFFFFFu, inc, off);
        if (lane >= off) inc += u;
    }
    int wexcl = inc - tsum;

    __shared__ int ws[8], wo[8];
    if (lane == 31) ws[wid] = inc;
    __syncthreads();
    if (tid < 8) {
        int e = 0;
        for (int k = 0; k < tid; k++) e += ws[k];
        wo[tid] = e;
    }
    __syncthreads();

    int off0 = boffs[blockIdx.x] + wo[wid] + wexcl;
    #pragma unroll
    for (int j = 0; j < 8; j++) {
        int idx = base + j;
        if (idx < NNODES) {
            int e = off0 + v[j];
            start[idx]  = e;
            cursor[idx] = e;
        }
    }
}

__global__ void scatter_kernel(const int* __restrict__ row, const int* __restrict__ col,
                               int E, int* __restrict__ cursor, int* __restrict__ colS) {
    for (int e = blockIdx.x * blockDim.x + threadIdx.x; e < E; e += gridDim.x * blockDim.x) {
        int r = row[e];
        int pos = atomicAdd(&cursor[r], 1);
        colS[pos] = col[e];
    }
}

// ---------------------------------------------------------------------------
// Fused per-iteration kernel: one warp per destination node.
// R13 pipeline structure (4-edge batch, prefetch next batch during compute)
// + warp-register column buffer: one coalesced LDG per 32 edges, shfl
// broadcast -> the tail-gather address is ready instantly (no dependent
// colS scalar load inside the prefetch block).
// ---------------------------------------------------------------------------
__global__ void __launch_bounds__(256)
fused_edge_norm(const float* __restrict__ head_src,
                const float* __restrict__ fac,
                const __half* __restrict__ fach,
                const int* __restrict__ start,
                const int* __restrict__ colS,
                float* __restrict__ out) {
    const int lane = threadIdx.x & 31;
    const int n = (blockIdx.x * blockDim.x + threadIdx.x) >> 5;
    if (n >= NNODES) return;

    const size_t base = (size_t)n * DIM;
    float4 h = __ldg((const float4*)(head_src + base) + lane);
    int s     = __ldg(start + n);
    int e_end = __ldg(start + n + 1);

    const uint2* th = (const uint2*)fach;

    float4 acc = make_float4(0.f, 0.f, 0.f, 0.f);

    for (int chunk = s; chunk < e_end; chunk += 32) {
        int cnt = e_end - chunk; if (cnt > 32) cnt = 32;
        // one coalesced load fetches this chunk's column indices into registers
        int myc = (lane < cnt) ? __ldg(colS + chunk + lane) : 0;

        uint2 cur[4], nxt[4];
        // prime the pipeline: first batch of this chunk
        {
            int nb = cnt; if (nb > 4) nb = 4;
            #pragma unroll
            for (int j = 0; j < 4; j++) {
                if (j < nb) {
                    int c = __shfl_sync(0xFFFFFFFFu, myc, j);
                    cur[j] = __ldg(th + (size_t)c * 32 + lane);
                } else {
                    cur[j] = make_uint2(0u, 0u);
                }
            }
        }

        for (int j0 = 0; j0 < cnt; j0 += 4) {
            int nb  = cnt - j0;        if (nb > 4)  nb = 4;
            int nnx = cnt - (j0 + 4);  if (nnx > 4) nnx = 4;

            // prefetch next batch (addresses from registers — zero load dep)
            #pragma unroll
            for (int j = 0; j < 4; j++) {
                if (j < nnx) {
                    int c = __shfl_sync(0xFFFFFFFFu, myc, j0 + 4 + j);
                    nxt[j] = __ldg(th + (size_t)c * 32 + lane);
                } else {
                    nxt[j] = make_uint2(0u, 0u);
                }
            }

            // 4 interleaved dot/softmax chains (padding gives dp=0, harmless)
            float2 f0[4], f1[4];
            float dp[4];
            #pragma unroll
            for (int j = 0; j < 4; j++) {
                f0[j] = __half22float2(*(__half2*)&cur[j].x);
                f1[j] = __half22float2(*(__half2*)&cur[j].y);
                dp[j] = h.x*f0[j].x + h.y*f0[j].y + h.z*f1[j].x + h.w*f1[j].y;
            }
            #pragma unroll
            for (int j = 0; j < 4; j++) dp[j] += __shfl_xor_sync(0xFFFFFFFFu, dp[j], 1);
            #pragma unroll
            for (int j = 0; j < 4; j++) dp[j] += __shfl_xor_sync(0xFFFFFFFFu, dp[j], 2);
            #pragma unroll
            for (int j = 0; j < 4; j++) dp[j] += __shfl_xor_sync(0xFFFFFFFFu, dp[j], 4);
            float ea[4], s1[4], st[4];
            #pragma unroll
            for (int j = 0; j < 4; j++) ea[j] = __expf(dp[j]);
            #pragma unroll
            for (int j = 0; j < 4; j++) s1[j] = ea[j] + __shfl_xor_sync(0xFFFFFFFFu, ea[j], 8);
            #pragma unroll
            for (int j = 0; j < 4; j++) st[j] = s1[j] + __shfl_xor_sync(0xFFFFFFFFu, s1[j], 16);
            #pragma unroll
            for (int j = 0; j < 4; j++) {
                if (j < nb) {
                    float p = __fdividef(ea[j], st[j]);
                    acc.x += p * f0[j].x; acc.y += p * f0[j].y;
                    acc.z += p * f1[j].x; acc.w += p * f1[j].y;
                }
            }

            #pragma unroll
            for (int j = 0; j < 4; j++) cur[j] = nxt[j];
        }
    }

    // residual base is ALWAYS the original fac (both iterations), fp32-exact
    float4 f = (head_src == fac) ? h : __ldg((const float4*)(fac + base) + lane);
    float4 v = make_float4(f.x + acc.x, f.y + acc.y, f.z + acc.z, f.w + acc.w);
    float ss = v.x*v.x + v.y*v.y + v.z*v.z + v.w*v.w;
    ss += __shfl_xor_sync(0xFFFFFFFFu, ss, 1);
    ss += __shfl_xor_sync(0xFFFFFFFFu, ss, 2);
    ss += __shfl_xor_sync(0xFFFFFFFFu, ss, 4);
    float inv = 1.0f / fmaxf(sqrtf(ss), 1e-12f);
    v.x *= inv; v.y *= inv; v.z *= inv; v.w *= inv;
    ((float4*)(out + base))[lane] = v;
}

// ---------------------------------------------------------------------------
extern "C" void kernel_launch(void* const* d_in, const int* in_sizes, int n_in,
                              void* d_out, int out_size) {
    const float* all_emb = (const float*)d_in[0];
    const float* W       = (const float*)d_in[1];
    const float* b       = (const float*)d_in[2];
    const int*   row     = (const int*)  d_in[3];
    const int*   col     = (const int*)  d_in[4];
    int          E       = in_sizes[3];
    if (E > EMAX) E = EMAX;
    float*       out     = (float*)d_out;

    float *fac, *nf;
    __half* fach;
    int *deg, *start, *cursor, *colS, *bsums, *boffs;
    cudaGetSymbolAddress((void**)&fac,    g_fac);
    cudaGetSymbolAddress((void**)&nf,     g_new);
    cudaGetSymbolAddress((void**)&fach,   g_fach);
    cudaGetSymbolAddress((void**)&deg,    g_deg);
    cudaGetSymbolAddress((void**)&start,  g_start);
    cudaGetSymbolAddress((void**)&cursor, g_cursor);
    cudaGetSymbolAddress((void**)&colS,   g_colS);
    cudaGetSymbolAddress((void**)&bsums,  g_bsums);
    cudaGetSymbolAddress((void**)&boffs,  g_boffs);

    const int smem = (DIM * DIM + 64 * DIM) * sizeof(float);  // 96 KB
    cudaFuncSetAttribute(gemm_kernel, cudaFuncAttributeMaxDynamicSharedMemorySize, smem);

    // Phase 1: factor embeddings (fp32x2 packed FMA) + fp16 tail table
    gemm_kernel<<<1563, 256, smem>>>(all_emb, W, b, fac, fach);

    // Phase 2: CSR build (row/col identical for both iterations -> build once)
    zero_deg_kernel<<<(NNODES + 255) / 256, 256>>>(deg);
    hist_kernel<<<2048, 256>>>(row, E, deg);
    scan_partial_kernel<<<SCAN_NBLK, 256>>>(deg, bsums);
    scan_sums_kernel<<<1, 64>>>(bsums, boffs, start);
    scan_final_kernel<<<SCAN_NBLK, 256>>>(deg, boffs, start, cursor);
    scatter_kernel<<<2048, 256>>>(row, col, E, cursor, colS);

    // Phase 3: two fused propagate+norm iterations (warp per node)
    const int blocks = (NNODES * 32 + 255) / 256;   // 12500
    fused_edge_norm<<<blocks, 256>>>(fac, fac, fach, start, colS, nf);
    fused_edge_norm<<<blocks, 256>>>(nf,  fac, fach, start, colS, out);
}